// round 12
// baseline (speedup 1.0000x reference)
#include <cuda_runtime.h>
#include <cuda_bf16.h>
#include <cstdint>
#include <math.h>

#define DINL __device__ __forceinline__
DINL float sigm(float x) { return 1.0f / (1.0f + expf(-x)); }

// ---------------- scratch (__device__ globals, no allocation) ---------------
__device__ float g_pool1[31 * 255 * 256];     // stft conv1+pool
__device__ float g_pool2[14 * 126 * 256];     // stft conv2+pool  (== Xs[14][32256])
__device__ float g_partial[64 * 14 * 1024];   // s_Wi GEMM k-split partials
__device__ float g_xbs[14 * 1024];            // stft lstm input preact (+bias)
__device__ float g_wpool1[127 * 256];
__device__ float g_wpool2[62 * 256];
__device__ float g_xbw[62 * 1024];            // wave lstm input preact (+bias)
__device__ float g_sh[256], g_sc[256], g_whh[256], g_wc[256];
__device__ float g_h0[256], g_c0[256];        // decoder init state
__device__ float g_xiR[2 * 1024];             // xi[tok] rearranged per cluster rank
__device__ float g_WhR[8 * 256 * 128];        // d_Wh rearranged per-rank slices
__device__ float g_hs[38272 * 256];           // all decoder hidden states

// ============ STFT conv1 3x3 (1->256) + relu + maxpool 2x2 ===================
__global__ void __launch_bounds__(256) k_sconv1(const float* __restrict__ in,
                                                const float* __restrict__ w,
                                                const float* __restrict__ b) {
    const int blk = blockIdx.x;
    const int tp = blk / 255, fp = blk % 255;
    __shared__ float patch[4][4];
    const int tid = threadIdx.x;
    if (tid < 16) {
        int rr = tid >> 2, cc = tid & 3;
        patch[rr][cc] = in[(2 * tp + rr) * 513 + (2 * fp + cc)];
    }
    __syncthreads();
    const int ch = tid;
    float wr[9];
#pragma unroll
    for (int t = 0; t < 9; ++t) wr[t] = w[t * 256 + ch];
    const float bb = b[ch];
    float best = -1e30f;
#pragma unroll
    for (int a = 0; a < 2; ++a)
#pragma unroll
        for (int bc = 0; bc < 2; ++bc) {
            float acc = bb;
#pragma unroll
            for (int i = 0; i < 3; ++i)
#pragma unroll
                for (int j = 0; j < 3; ++j)
                    acc = fmaf(patch[a + i][bc + j], wr[i * 3 + j], acc);
            best = fmaxf(best, fmaxf(acc, 0.0f));
        }
    g_pool1[(tp * 255 + fp) * 256 + ch] = best;
}

// ============ STFT conv2 3x3 (256->256) + relu + maxpool 2x2 =================
// grid (42, 14): 3 pooled-f positions per block, 1 pooled-t row
__global__ void __launch_bounds__(256) k_sconv2(const float* __restrict__ w2,
                                                const float* __restrict__ b2) {
    __shared__ float sin_[4 * 8 * 256];
    const int tp = blockIdx.y;
    const int fp0 = blockIdx.x * 3;
    const int tid = threadIdx.x;
    for (int idx = tid; idx < 4 * 8 * 256; idx += 256) {
        int ch = idx & 255;
        int col = (idx >> 8) & 7;
        int row = idx >> 11;
        sin_[idx] = g_pool1[((2 * tp + row) * 255 + (2 * fp0 + col)) * 256 + ch];
    }
    __syncthreads();
    const int ch = tid;
    float a[2][6];
    const float bb = b2[ch];
#pragma unroll
    for (int r2 = 0; r2 < 2; ++r2)
#pragma unroll
        for (int cc = 0; cc < 6; ++cc) a[r2][cc] = bb;
    for (int ic = 0; ic < 256; ++ic) {
        float rv[4][8];
#pragma unroll
        for (int rr = 0; rr < 4; ++rr)
#pragma unroll
            for (int cc = 0; cc < 8; ++cc) rv[rr][cc] = sin_[(rr * 8 + cc) * 256 + ic];
#pragma unroll
        for (int i = 0; i < 3; ++i)
#pragma unroll
            for (int j = 0; j < 3; ++j) {
                float wv = w2[((i * 3 + j) * 256 + ic) * 256 + ch];
#pragma unroll
                for (int r2 = 0; r2 < 2; ++r2)
#pragma unroll
                    for (int cc = 0; cc < 6; ++cc)
                        a[r2][cc] = fmaf(wv, rv[r2 + i][cc + j], a[r2][cc]);
            }
    }
#pragma unroll
    for (int cc2 = 0; cc2 < 3; ++cc2) {
        float m = -1e30f;
#pragma unroll
        for (int r2 = 0; r2 < 2; ++r2)
#pragma unroll
            for (int q = 0; q < 2; ++q)
                m = fmaxf(m, fmaxf(a[r2][2 * cc2 + q], 0.0f));
        g_pool2[(tp * 126 + (fp0 + cc2)) * 256 + ch] = m;
    }
}

// ============ wave conv1 k3 (1024->256) + relu + pool2 =======================
__global__ void __launch_bounds__(256) k_wconv1(const float* __restrict__ in,
                                                const float* __restrict__ w,
                                                const float* __restrict__ b) {
    __shared__ float sw[4][1024];
    const int tp = blockIdx.x;
    const int tid = threadIdx.x;
    for (int idx = tid; idx < 4096; idx += 256) {
        int r = idx >> 10, k = idx & 1023;
        sw[r][k] = in[(2 * tp + r) * 1024 + k];
    }
    __syncthreads();
    const int ch = tid;
    float a0 = b[ch], a1 = b[ch];
    for (int dt = 0; dt < 3; ++dt)
        for (int k = 0; k < 1024; ++k) {
            float wv = w[(dt * 1024 + k) * 256 + ch];
            a0 = fmaf(wv, sw[dt][k], a0);
            a1 = fmaf(wv, sw[dt + 1][k], a1);
        }
    g_wpool1[tp * 256 + ch] = fmaxf(fmaxf(a0, 0.0f), fmaxf(a1, 0.0f));
}

// ============ wave conv2 k3 (256->256) + relu + pool2 ========================
__global__ void __launch_bounds__(256) k_wconv2(const float* __restrict__ w,
                                                const float* __restrict__ b) {
    __shared__ float sw[4][256];
    const int tp = blockIdx.x;
    const int tid = threadIdx.x;
    for (int idx = tid; idx < 1024; idx += 256) {
        int r = idx >> 8, k = idx & 255;
        sw[r][k] = g_wpool1[(2 * tp + r) * 256 + k];
    }
    __syncthreads();
    const int ch = tid;
    float a0 = b[ch], a1 = b[ch];
    for (int dt = 0; dt < 3; ++dt)
        for (int k = 0; k < 256; ++k) {
            float wv = w[(dt * 256 + k) * 256 + ch];
            a0 = fmaf(wv, sw[dt][k], a0);
            a1 = fmaf(wv, sw[dt + 1][k], a1);
        }
    g_wpool2[tp * 256 + ch] = fmaxf(fmaxf(a0, 0.0f), fmaxf(a1, 0.0f));
}

// ============ Xs[14,32256] @ s_Wi[32256,1024]: k-split partials ==============
__global__ void __launch_bounds__(256) k_sproj(const float* __restrict__ sWi) {
    __shared__ float xs[14 * 504];
    const int j = blockIdx.x * 256 + threadIdx.x;
    const int k0 = blockIdx.y * 504;
    for (int idx = threadIdx.x; idx < 14 * 504; idx += 256) {
        int t = idx / 504, kk = idx % 504;
        xs[idx] = g_pool2[t * 32256 + k0 + kk];
    }
    __syncthreads();
    float acc[14];
#pragma unroll
    for (int t = 0; t < 14; ++t) acc[t] = 0.f;
    for (int kk = 0; kk < 504; ++kk) {
        float wv = sWi[(size_t)(k0 + kk) * 1024 + j];
#pragma unroll
        for (int t = 0; t < 14; ++t) acc[t] = fmaf(xs[t * 504 + kk], wv, acc[t]);
    }
    for (int t = 0; t < 14; ++t)
        g_partial[(blockIdx.y * 14 + t) * 1024 + j] = acc[t];
}

__global__ void __launch_bounds__(256) k_sreduce(const float* __restrict__ sb) {
    const int idx = blockIdx.x * 256 + threadIdx.x;  // 14336 total
    const int t = idx >> 10, j = idx & 1023;
    float a = sb[j];
    for (int kc = 0; kc < 64; ++kc) a += g_partial[(kc * 14 + t) * 1024 + j];
    g_xbs[t * 1024 + j] = a;
}

// ============ wave Wi projection: yw[62,256] @ w_Wi[256,1024] + b ============
__global__ void __launch_bounds__(1024) k_wproj(const float* __restrict__ wWi,
                                                const float* __restrict__ wb) {
    __shared__ float yr[256];
    const int tid = threadIdx.x;
    if (tid < 256) yr[tid] = g_wpool2[blockIdx.x * 256 + tid];
    __syncthreads();
    float a = wb[tid];
    for (int k = 0; k < 256; ++k) a = fmaf(yr[k], wWi[k * 1024 + tid], a);
    g_xbw[blockIdx.x * 1024 + tid] = a;
}

// ============ small sequential LSTM (encoders), 1 block x 1024 ===============
// mode 0: stft (T=14, xpre=g_xbs, out g_sh/g_sc); mode 1: wave (T=62, g_xbw)
__global__ void __launch_bounds__(1024) k_lstm_small(const float* __restrict__ Wh,
                                                     int mode) {
    __shared__ float h[256];
    __shared__ float zsm[1024];
    const int tid = threadIdx.x;
    const int T = mode ? 62 : 14;
    const float* xpre = mode ? g_xbw : g_xbs;
    float c = 0.0f;
    if (tid < 256) h[tid] = 0.0f;
    __syncthreads();
    for (int t = 0; t < T; ++t) {
        float acc = xpre[t * 1024 + tid];
#pragma unroll 8
        for (int k = 0; k < 256; ++k) acc = fmaf(h[k], Wh[k * 1024 + tid], acc);
        zsm[tid] = acc;
        __syncthreads();
        if (tid < 256) {
            float zi = zsm[tid], zf = zsm[256 + tid], zg = zsm[512 + tid], zo = zsm[768 + tid];
            c = sigm(zf) * c + sigm(zi) * tanhf(zg);
            h[tid] = sigm(zo) * tanhf(c);
        }
        __syncthreads();
    }
    if (tid < 256) {
        if (mode) { g_whh[tid] = h[tid]; g_wc[tid] = c; }
        else      { g_sh[tid]  = h[tid]; g_sc[tid] = c; }
    }
}

// ============ state reducers =================================================
__global__ void __launch_bounds__(256) k_reduce(const float* __restrict__ rhw,
                                                const float* __restrict__ rhb,
                                                const float* __restrict__ rcw,
                                                const float* __restrict__ rcb) {
    __shared__ float hcat[512], ccat[512];
    const int tid = threadIdx.x;
    hcat[tid] = g_sh[tid];  hcat[256 + tid] = g_whh[tid];
    ccat[tid] = g_sc[tid];  ccat[256 + tid] = g_wc[tid];
    __syncthreads();
    float ah = rhb[tid], ac = rcb[tid];
    for (int k = 0; k < 512; ++k) {
        ah = fmaf(hcat[k], rhw[k * 256 + tid], ah);
        ac = fmaf(ccat[k], rcw[k * 256 + tid], ac);
    }
    g_h0[tid] = ah;
    g_c0[tid] = ac;
}

// ============ decoder prep: xi[tok] = emb[tok]@d_Wi + d_b, rank-rearranged ===
__global__ void __launch_bounds__(1024) k_dprep(const float* __restrict__ emb,
                                                const float* __restrict__ dWi,
                                                const float* __restrict__ db) {
    __shared__ float er[256];
    const int tid = threadIdx.x;
    if (tid < 256) er[tid] = emb[blockIdx.x * 256 + tid];
    __syncthreads();
    float a = db[tid];
    for (int d = 0; d < 256; ++d) a = fmaf(er[d], dWi[d * 1024 + tid], a);
    int gate = tid >> 8, cg = tid & 255, r = cg >> 5, u = cg & 31;
    g_xiR[blockIdx.x * 1024 + r * 128 + gate * 32 + u] = a;
}

// ============ d_Wh rearrange into per-rank slices ============================
// rank r owns cells u_g = r*32..r*32+31, all 4 gates. local col jl = gate*32+u.
__global__ void __launch_bounds__(1024) k_whprep(const float* __restrict__ dWh) {
    const int k = blockIdx.x, j = threadIdx.x;
    int gate = j >> 8, cg = j & 255, r = cg >> 5, u = cg & 31;
    g_WhR[r * 32768 + k * 128 + gate * 32 + u] = dWh[k * 1024 + j];
}

// ============ persistent decoder: 8-CTA cluster, 38272 LSTM steps ============
__global__ void __cluster_dims__(8, 1, 1) __launch_bounds__(128, 1)
k_decoder(const float* __restrict__ dec) {
    extern __shared__ float sm[];
    float* W = sm;                         // [256][128] rank slice
    float* hb0 = sm + 32768;               // h double buffer
    float* hb1 = sm + 33024;
    float* xis = sm + 33280;               // [2][128]
    float* zs = sm + 33536;                // [128]
    const int r = blockIdx.x;
    const int jl = threadIdx.x;

    for (int idx = jl; idx < 32768; idx += 128) W[idx] = g_WhR[r * 32768 + idx];
    xis[jl] = g_xiR[r * 128 + jl];
    xis[128 + jl] = g_xiR[1024 + r * 128 + jl];
    hb0[jl] = g_h0[jl];
    hb0[128 + jl] = g_h0[128 + jl];
    float c = (jl < 32) ? g_c0[r * 32 + jl] : 0.0f;

    asm volatile("barrier.cluster.arrive.aligned;" ::: "memory");
    asm volatile("barrier.cluster.wait.aligned;" ::: "memory");

    int p = 0;
    for (int s = 0; s < 38272; ++s) {
        const float* hcur = p ? hb1 : hb0;
        float* hnxt = p ? hb0 : hb1;
        const int tok = (dec[s] > 0.5f) ? 1 : 0;
        float acc = xis[tok * 128 + jl];
        const float4* h4 = (const float4*)hcur;
#pragma unroll 4
        for (int k4 = 0; k4 < 64; ++k4) {
            float4 hv = h4[k4];
            acc = fmaf(hv.x, W[(k4 * 4 + 0) * 128 + jl], acc);
            acc = fmaf(hv.y, W[(k4 * 4 + 1) * 128 + jl], acc);
            acc = fmaf(hv.z, W[(k4 * 4 + 2) * 128 + jl], acc);
            acc = fmaf(hv.w, W[(k4 * 4 + 3) * 128 + jl], acc);
        }
        zs[jl] = acc;
        __syncthreads();
        if (jl < 32) {
            float zi = zs[jl], zf = zs[32 + jl], zg = zs[64 + jl], zo = zs[96 + jl];
            c = sigm(zf) * c + sigm(zi) * tanhf(zg);
            float hn = sigm(zo) * tanhf(c);
            g_hs[(size_t)s * 256 + r * 32 + jl] = hn;
            uint32_t la = (uint32_t)__cvta_generic_to_shared(&hnxt[r * 32 + jl]);
#pragma unroll
            for (int rr = 0; rr < 8; ++rr) {
                uint32_t ra;
                asm volatile("mapa.shared::cluster.u32 %0, %1, %2;"
                             : "=r"(ra) : "r"(la), "r"(rr));
                asm volatile("st.shared::cluster.f32 [%0], %1;"
                             :: "r"(ra), "f"(hn) : "memory");
            }
        }
        asm volatile("barrier.cluster.arrive.aligned;" ::: "memory");
        asm volatile("barrier.cluster.wait.aligned;" ::: "memory");
        p ^= 1;
    }
}

// ============ epilogue: softmax(hs @ out_w + out_b), 4 steps per block =======
__global__ void __launch_bounds__(128) k_softmax(const float* __restrict__ ow,
                                                 const float* __restrict__ ob,
                                                 float* __restrict__ out) {
    __shared__ float hsr[4 * 256];
    __shared__ float red[128];
    const int s0 = blockIdx.x * 4;
    const int w = threadIdx.x;
    for (int idx = w; idx < 1024; idx += 128) hsr[idx] = g_hs[(size_t)s0 * 256 + idx];
    __syncthreads();
    float a[4];
    const float bb = ob[w];
#pragma unroll
    for (int i = 0; i < 4; ++i) a[i] = bb;
    for (int d = 0; d < 256; ++d) {
        float wv = ow[d * 128 + w];
#pragma unroll
        for (int i = 0; i < 4; ++i) a[i] = fmaf(hsr[i * 256 + d], wv, a[i]);
    }
#pragma unroll
    for (int i = 0; i < 4; ++i) {
        red[w] = a[i];
        __syncthreads();
        for (int off = 64; off; off >>= 1) {
            if (w < off) red[w] = fmaxf(red[w], red[w + off]);
            __syncthreads();
        }
        float m = red[0];
        __syncthreads();
        float e = expf(a[i] - m);
        red[w] = e;
        __syncthreads();
        for (int off = 64; off; off >>= 1) {
            if (w < off) red[w] += red[w + off];
            __syncthreads();
        }
        float ssum = red[0];
        __syncthreads();
        int s = s0 + i, t = s >> 7, v = s & 127;
        out[((size_t)v * 300 + t) * 128 + w] = e / ssum;
    }
}

// ============ zero the unwritten last time slot out[:,299,:] =================
__global__ void __launch_bounds__(256) k_zero(float* __restrict__ out) {
    const int idx = blockIdx.x * 256 + threadIdx.x;  // 16384
    const int v = idx >> 7, w = idx & 127;
    out[((size_t)v * 300 + 299) * 128 + w] = 0.0f;
}

// ============================================================================
extern "C" void kernel_launch(void* const* d_in, const int* in_sizes, int n_in,
                              void* d_out, int out_size) {
    const float* stft = (const float*)d_in[0];
    const float* wave = (const float*)d_in[1];
    const float* dec  = (const float*)d_in[2];
    const float* scw1 = (const float*)d_in[3];
    const float* scb1 = (const float*)d_in[4];
    const float* scw2 = (const float*)d_in[5];
    const float* scb2 = (const float*)d_in[6];
    const float* sWi  = (const float*)d_in[7];
    const float* sWh  = (const float*)d_in[8];
    const float* sb   = (const float*)d_in[9];
    const float* wcw1 = (const float*)d_in[10];
    const float* wcb1 = (const float*)d_in[11];
    const float* wcw2 = (const float*)d_in[12];
    const float* wcb2 = (const float*)d_in[13];
    const float* wWi  = (const float*)d_in[14];
    const float* wWh  = (const float*)d_in[15];
    const float* wb   = (const float*)d_in[16];
    const float* rhw  = (const float*)d_in[17];
    const float* rhb  = (const float*)d_in[18];
    const float* rcw  = (const float*)d_in[19];
    const float* rcb  = (const float*)d_in[20];
    const float* emb  = (const float*)d_in[21];
    const float* dWi  = (const float*)d_in[22];
    const float* dWh  = (const float*)d_in[23];
    const float* db   = (const float*)d_in[24];
    const float* ow   = (const float*)d_in[25];
    const float* ob   = (const float*)d_in[26];
    float* out = (float*)d_out;
    (void)in_sizes; (void)n_in; (void)out_size; (void)wb;

    cudaFuncSetAttribute(k_decoder, cudaFuncAttributeMaxDynamicSharedMemorySize, 134656);

    // ---- STFT encoder ----
    k_sconv1<<<31 * 255, 256>>>(stft, scw1, scb1);
    k_sconv2<<<dim3(42, 14), 256>>>(scw2, scb2);
    k_sproj<<<dim3(4, 64), 256>>>(sWi);
    k_sreduce<<<56, 256>>>(sb);
    k_lstm_small<<<1, 1024>>>(sWh, 0);

    // ---- waveform encoder ----
    k_wconv1<<<127, 256>>>(wave, wcw1, wcb1);
    k_wconv2<<<62, 256>>>(wcw2, wcb2);
    k_wproj<<<62, 1024>>>(wWi, wb);
    k_lstm_small<<<1, 1024>>>(wWh, 1);

    // ---- reducers + decoder prep ----
    k_reduce<<<1, 256>>>(rhw, rhb, rcw, rcb);
    k_dprep<<<2, 1024>>>(emb, dWi, db);
    k_whprep<<<256, 1024>>>(dWh);

    // ---- sequential decoder (8-CTA cluster, persistent) ----
    k_decoder<<<8, 128, 134656>>>(dec);

    // ---- parallel softmax epilogue + zero last slot ----
    k_softmax<<<9568, 128>>>(ow, ob, out);
    k_zero<<<64, 256>>>(out);
}